// round 7
// baseline (speedup 1.0000x reference)
#include <cuda_runtime.h>
#include <cuda_bf16.h>
#include <cuda_fp16.h>
#include <cstdint>
#include <math.h>

#define VOCABSZ 32000
#define VPAD    32128
#define WORDVEC 256
#define HIDDEN  512
#define TSTEPS  256
#define NBATCH  16
#define G4      2048
#define MROWS   4096
#define NGRP    4
#define GCOLS   8000
#define VTILES  63
#define LOG2E   1.44269504f
#define SW_W    256.0f
#define SW_H    64.0f
#define V_SCL   ((float)(1.44269504 / 16384.0))   // LOG2E / (SW_W*SW_H)
#define T_SCL   (1.0f / 16384.0f)

// ---------------- device scratch ----------------
__device__ float          g_xw[TSTEPS * NBATCH * G4];
__device__ unsigned char  g_hq[MROWS * HIDDEN];            // fp8 h history (x64)
__device__ unsigned char  g_wv8[(size_t)VPAD * HIDDEN];    // Wv^T fp8 [v][k] (x256)
__device__ __nv_bfloat16  g_xb[MROWS * WORDVEC];           // gathered embeddings bf16
__device__ __nv_bfloat16  g_wxT[G4 * WORDVEC];             // Wx^T bf16
__device__ float          g_bv2[VPAD];                     // bv * LOG2E
__device__ float          g_hT2[2][HIDDEN * NBATCH];       // fp32 recurrent state [k][n]
__device__ unsigned       g_barc[256];
__device__ float          g_ps[NGRP * MROWS];
__device__ float          g_lt[MROWS];

// ---------------- helpers ----------------
__device__ __forceinline__ float sigf(float x) { return __fdividef(1.f, 1.f + __expf(-x)); }
__device__ __forceinline__ float tanhf_fast(float x) { return __fdividef(2.f, 1.f + __expf(-2.f * x)) - 1.f; }
__device__ __forceinline__ uint32_t smem_to_u32(const void* p) {
    uint32_t a;
    asm("{ .reg .u64 t; cvta.to.shared.u64 t, %1; cvt.u32.u64 %0, t; }" : "=r"(a) : "l"(p));
    return a;
}
// pack 2 floats -> 2 e4m3 (low byte = b, high byte = a)
__device__ __forceinline__ uint16_t f2_to_e4m3(float hi, float lo) {
    uint16_t r;
    asm("cvt.rn.satfinite.e4m3x2.f32 %0, %1, %2;" : "=h"(r) : "f"(hi), "f"(lo));
    return r;
}
__device__ __forceinline__ float2 e4m3x2_to_f2(uint16_t u) {
    uint32_t h2;
    asm("cvt.rn.f16x2.e4m3x2 %0, %1;" : "=r"(h2) : "h"(u));
    __half2 hh = *reinterpret_cast<__half2*>(&h2);
    return __half22float2(hh);
}
#define LDSM_X4(r, addr) asm volatile( \
    "ldmatrix.sync.aligned.m8n8.x4.shared.b16 {%0,%1,%2,%3}, [%4];" \
    : "=r"((r)[0]), "=r"((r)[1]), "=r"((r)[2]), "=r"((r)[3]) : "r"(addr))
#define MMA16816(d, a, b0, b1) asm volatile( \
    "mma.sync.aligned.m16n8k16.row.col.f32.bf16.bf16.f32 " \
    "{%0,%1,%2,%3}, {%4,%5,%6,%7}, {%8,%9}, {%0,%1,%2,%3};" \
    : "+f"((d)[0]), "+f"((d)[1]), "+f"((d)[2]), "+f"((d)[3]) \
    : "r"((a)[0]), "r"((a)[1]), "r"((a)[2]), "r"((a)[3]), "r"(b0), "r"(b1))
#define MMA16832(d, a, b0, b1) asm volatile( \
    "mma.sync.aligned.m16n8k32.row.col.f32.e4m3.e4m3.f32 " \
    "{%0,%1,%2,%3}, {%4,%5,%6,%7}, {%8,%9}, {%0,%1,%2,%3};" \
    : "+f"((d)[0]), "+f"((d)[1]), "+f"((d)[2]), "+f"((d)[3]) \
    : "r"((a)[0]), "r"((a)[1]), "r"((a)[2]), "r"((a)[3]), "r"(b0), "r"(b1))

__device__ __forceinline__ float exp2_fast(float t) {
    int i = __float2int_rn(t);
    float f = t - (float)i;
    float p = fmaf(f, 0.00133335581f, 0.00961812911f);
    p = fmaf(f, p, 0.0555041087f);
    p = fmaf(f, p, 0.240226507f);
    p = fmaf(f, p, 0.693147181f);
    p = fmaf(f, p, 1.0f);
    return __int_as_float(__float_as_int(p) + (i << 23));
}

__device__ __forceinline__ void grid_barrier(int idx, unsigned nblocks) {
    __threadfence();
    __syncthreads();
    if (threadIdx.x == 0) {
        atomicAdd(&g_barc[idx], 1u);
        volatile unsigned* p = &g_barc[idx];
        while (*p < nblocks) { }
        __threadfence();
    }
    __syncthreads();
}

// ---------------- init ----------------
__global__ void __launch_bounds__(256) init_kernel(
    const float* __restrict__ h_init, const float* __restrict__ bv)
{
    int gid = blockIdx.x * 256 + threadIdx.x;            // 8192 threads
    if (gid < 256) g_barc[gid] = 0u;
    if (gid < HIDDEN * NBATCH) g_hT2[0][gid] = h_init[gid >> 4];
    for (int j = gid; j < (VPAD - VOCABSZ) * HIDDEN; j += 8192)
        g_wv8[(size_t)VOCABSZ * HIDDEN + j] = 0;
    for (int j = gid; j < VPAD; j += 8192)
        g_bv2[j] = (j < VOCABSZ) ? bv[j] * LOG2E : 0.f;
}

// ---------------- Wv transpose + fp8 (x256): [512,32000] -> [32000,512] ----------------
__global__ void __launch_bounds__(256) conv_wv_kernel(const float* __restrict__ Wv) {
    __shared__ float sh[32 * 33];
    int n0 = blockIdx.x * 32, k0 = blockIdx.y * 32;
    int tx = threadIdx.x & 31, ty = threadIdx.x >> 5;
    #pragma unroll
    for (int i = 0; i < 4; ++i) {
        int k = ty + i * 8;
        sh[k * 33 + tx] = Wv[(size_t)(k0 + k) * VOCABSZ + n0 + tx];
    }
    __syncthreads();
    if (tx < 16) {
        #pragma unroll
        for (int i = 0; i < 4; ++i) {
            int n = ty + i * 8;
            float v0 = sh[(2 * tx + 0) * 33 + n] * SW_W;
            float v1 = sh[(2 * tx + 1) * 33 + n] * SW_W;
            uint16_t u = f2_to_e4m3(v1, v0);
            *(uint16_t*)&g_wv8[(size_t)(n0 + n) * HIDDEN + k0 + 2 * tx] = u;
        }
    }
}

// ---------------- Wx transpose + bf16 ----------------
__global__ void __launch_bounds__(256) conv_wx_kernel(const float* __restrict__ Wx) {
    __shared__ float sh[32 * 33];
    int n0 = blockIdx.x * 32, k0 = blockIdx.y * 32;
    int tx = threadIdx.x & 31, ty = threadIdx.x >> 5;
    #pragma unroll
    for (int i = 0; i < 4; ++i) {
        int k = ty + i * 8;
        sh[k * 33 + tx] = Wx[(k0 + k) * G4 + n0 + tx];
    }
    __syncthreads();
    #pragma unroll
    for (int i = 0; i < 4; ++i) {
        int n = ty + i * 8;
        g_wxT[(n0 + n) * WORDVEC + k0 + tx] = __float2bfloat16(sh[tx * 33 + n]);
    }
}

// ---------------- gather embeddings -> bf16 ----------------
__global__ void __launch_bounds__(256) gather_x_kernel(
    const int* __restrict__ captions, const float* __restrict__ W_embed)
{
    int gid = blockIdx.x * 256 + threadIdx.x;
    int idx = gid * 4;
    int r = idx >> 8, d = idx & 255;
    int tok = captions[(r & 15) * 257 + (r >> 4)];
    float4 v = *(const float4*)&W_embed[tok * WORDVEC + d];
    __nv_bfloat16 o[4];
    o[0] = __float2bfloat16(v.x); o[1] = __float2bfloat16(v.y);
    o[2] = __float2bfloat16(v.z); o[3] = __float2bfloat16(v.w);
    *(uint2*)&g_xb[idx] = *(const uint2*)o;
}

// ---------------- embed GEMM (bf16 mma.sync) ----------------
#define E_A_STRIDE 264
#define E_B_OFF    67584
#define E_SMEM     135168
extern __shared__ __align__(16) char dsm_e[];
__global__ void __launch_bounds__(256, 1) embed_mma_kernel(const float* __restrict__ b) {
    __nv_bfloat16* As = (__nv_bfloat16*)dsm_e;
    __nv_bfloat16* Bs = (__nv_bfloat16*)(dsm_e + E_B_OFF);
    const int tid = threadIdx.x, lane = tid & 31, wid = tid >> 5;
    const int wm = wid >> 1, wn = wid & 1;
    const int mblk = blockIdx.x >> 4, nblk = blockIdx.x & 15;

    const uint4* asrc = (const uint4*)(g_xb + mblk * 128 * WORDVEC);
    const uint4* bsrc = (const uint4*)(g_wxT + nblk * 128 * WORDVEC);
    #pragma unroll
    for (int q = 0; q < 16; ++q) {
        int i = q * 256 + tid;
        int r = i >> 5, u = i & 31;
        *(uint4*)(As + r * E_A_STRIDE + u * 8) = asrc[i];
        *(uint4*)(Bs + r * E_A_STRIDE + u * 8) = bsrc[i];
    }
    __syncthreads();

    const uint32_t a_base = smem_to_u32(As);
    const uint32_t a_lane = (uint32_t)((lane & 15) * E_A_STRIDE + (lane >> 4) * 8) * 2;
    const int bq = lane >> 3;
    const uint32_t b_lane = (uint32_t)(((bq >> 1) * 8 + (lane & 7)) * E_A_STRIDE + (bq & 1) * 8) * 2;
    const uint32_t b_base = smem_to_u32(Bs) + (uint32_t)(wn * 64 * E_A_STRIDE) * 2;

    float d[2][8][4];
    #pragma unroll
    for (int mt = 0; mt < 2; ++mt)
        #pragma unroll
        for (int nt = 0; nt < 8; ++nt)
            #pragma unroll
            for (int e = 0; e < 4; ++e) d[mt][nt][e] = 0.f;

    #pragma unroll
    for (int k16 = 0; k16 < 16; ++k16) {
        const uint32_t koff = (uint32_t)(k16 * 16) * 2;
        uint32_t a[2][4];
        #pragma unroll
        for (int mt = 0; mt < 2; ++mt) {
            LDSM_X4(a[mt], a_base + a_lane + (uint32_t)((wm * 32 + mt * 16) * E_A_STRIDE) * 2 + koff);
        }
        #pragma unroll
        for (int np = 0; np < 4; ++np) {
            uint32_t bb[4];
            LDSM_X4(bb, b_base + b_lane + (uint32_t)(np * 16 * E_A_STRIDE) * 2 + koff);
            MMA16816(d[0][np * 2 + 0], a[0], bb[0], bb[1]);
            MMA16816(d[0][np * 2 + 1], a[0], bb[2], bb[3]);
            MMA16816(d[1][np * 2 + 0], a[1], bb[0], bb[1]);
            MMA16816(d[1][np * 2 + 1], a[1], bb[2], bb[3]);
        }
    }

    const int cbase = nblk * 128 + wn * 64 + (lane & 3) * 2;
    #pragma unroll
    for (int mt = 0; mt < 2; ++mt)
        #pragma unroll
        for (int rh = 0; rh < 2; ++rh) {
            int row = mblk * 128 + wm * 32 + mt * 16 + rh * 8 + (lane >> 2);
            #pragma unroll
            for (int nt = 0; nt < 8; ++nt) {
                int c = cbase + nt * 8;
                float2 v;
                v.x = d[mt][nt][rh * 2 + 0] + b[c];
                v.y = d[mt][nt][rh * 2 + 1] + b[c + 1];
                *(float2*)&g_xw[(size_t)row * G4 + c] = v;
            }
        }
}

// ---------------- persistent LSTM (fp32 recurrence, fp8 history out) ----------------
extern __shared__ float dsm_l[];
__global__ void __launch_bounds__(256) lstm_kernel(const float* __restrict__ Wh) {
    float* Whs  = dsm_l;
    float* h_sh = dsm_l + 8192;
    float* part = dsm_l + 16384;
    float* a_sh = dsm_l + 20480;
    float* c_sh = dsm_l + 20736;

    const int bid = blockIdx.x, tid = threadIdx.x;
    const int h0 = bid * 4;
    const int kc = tid >> 4, j16 = tid & 15;

    for (int i = tid; i < 8192; i += 256) {
        int k = i >> 4, j = i & 15;
        int jcol = (j >> 2) * 512 + h0 + (j & 3);
        Whs[i] = Wh[k * G4 + jcol];
    }
    if (tid < 64) c_sh[tid] = 0.f;

    const int gn = tid >> 2, ghq = tid & 3;
    const int ghcol = h0 + ghq;

    for (int t = 0; t < TSTEPS; ++t) {
        float4* h4 = (float4*)h_sh;
        const float4* src4 = (const float4*)g_hT2[t & 1];
        #pragma unroll
        for (int i = 0; i < 8; ++i) h4[tid + i * 256] = __ldcg(&src4[tid + i * 256]);

        float xwv[4];
        if (tid < 64) {
            #pragma unroll
            for (int g = 0; g < 4; ++g)
                xwv[g] = g_xw[(size_t)(t * NBATCH + gn) * G4 + g * 512 + ghcol];
        }
        __syncthreads();

        float acc[16];
        #pragma unroll
        for (int n = 0; n < 16; ++n) acc[n] = 0.f;
        const float4* hp = (const float4*)h_sh + kc * 128;
        #pragma unroll 2
        for (int kk = 0; kk < 32; ++kk) {
            float w = Whs[(kc * 32 + kk) * 16 + j16];
            float4 a0 = hp[kk * 4 + 0], a1 = hp[kk * 4 + 1], a2 = hp[kk * 4 + 2], a3 = hp[kk * 4 + 3];
            acc[0]=fmaf(a0.x,w,acc[0]);  acc[1]=fmaf(a0.y,w,acc[1]);  acc[2]=fmaf(a0.z,w,acc[2]);  acc[3]=fmaf(a0.w,w,acc[3]);
            acc[4]=fmaf(a1.x,w,acc[4]);  acc[5]=fmaf(a1.y,w,acc[5]);  acc[6]=fmaf(a1.z,w,acc[6]);  acc[7]=fmaf(a1.w,w,acc[7]);
            acc[8]=fmaf(a2.x,w,acc[8]);  acc[9]=fmaf(a2.y,w,acc[9]);  acc[10]=fmaf(a2.z,w,acc[10]); acc[11]=fmaf(a2.w,w,acc[11]);
            acc[12]=fmaf(a3.x,w,acc[12]); acc[13]=fmaf(a3.y,w,acc[13]); acc[14]=fmaf(a3.z,w,acc[14]); acc[15]=fmaf(a3.w,w,acc[15]);
        }
        float4* pp = (float4*)(part + tid * 16);
        pp[0] = make_float4(acc[0], acc[1], acc[2], acc[3]);
        pp[1] = make_float4(acc[4], acc[5], acc[6], acc[7]);
        pp[2] = make_float4(acc[8], acc[9], acc[10], acc[11]);
        pp[3] = make_float4(acc[12], acc[13], acc[14], acc[15]);
        __syncthreads();

        float ssum = 0.f;
        #pragma unroll
        for (int q = 0; q < 16; ++q) ssum += part[q * 256 + tid];
        a_sh[tid] = ssum;
        __syncthreads();

        if (tid < 64) {
            float av0 = a_sh[(0 * 4 + ghq) * 16 + gn] + xwv[0];
            float av1 = a_sh[(1 * 4 + ghq) * 16 + gn] + xwv[1];
            float av2 = a_sh[(2 * 4 + ghq) * 16 + gn] + xwv[2];
            float av3 = a_sh[(3 * 4 + ghq) * 16 + gn] + xwv[3];
            float ig = sigf(av0), fg = sigf(av1), og = sigf(av2), gg = tanhf_fast(av3);
            float c  = fg * c_sh[tid] + ig * gg;
            float hh = og * tanhf_fast(c);
            c_sh[tid] = c;
            g_hT2[(t & 1) ^ 1][ghcol * 16 + gn] = hh;
            uint16_t p8 = f2_to_e4m3(0.f, hh * SW_H);
            g_hq[t * (NBATCH * HIDDEN) + gn * HIDDEN + ghcol] = (unsigned char)(p8 & 0xff);
        }
        grid_barrier(t, 128);
    }
}

// ---------------- target logits from fp8 operands (consistent with vocab GEMM) --------
__global__ void __launch_bounds__(256) tgt_kernel(
    const int* __restrict__ captions, const float* __restrict__ bv)
{
    int wid = threadIdx.x >> 5, lane = threadIdx.x & 31;
    int r = blockIdx.x * 8 + wid;
    int tg = captions[(r & 15) * 257 + (r >> 4) + 1];
    const uint32_t* hp = (const uint32_t*)(g_hq + (size_t)r * HIDDEN);
    const uint32_t* wp = (const uint32_t*)(g_wv8 + (size_t)tg * HIDDEN);
    float s = 0.f;
    #pragma unroll
    for (int i = 0; i < 4; ++i) {
        uint32_t h4 = hp[lane + i * 32];
        uint32_t w4 = wp[lane + i * 32];
        float2 ha = e4m3x2_to_f2((uint16_t)(h4 & 0xffff));
        float2 hb = e4m3x2_to_f2((uint16_t)(h4 >> 16));
        float2 wa = e4m3x2_to_f2((uint16_t)(w4 & 0xffff));
        float2 wb = e4m3x2_to_f2((uint16_t)(w4 >> 16));
        s = fmaf(ha.x, wa.x, s); s = fmaf(ha.y, wa.y, s);
        s = fmaf(hb.x, wb.x, s); s = fmaf(hb.y, wb.y, s);
    }
    #pragma unroll
    for (int o = 16; o > 0; o >>= 1) s += __shfl_xor_sync(0xffffffffu, s, o);
    if (lane == 0) g_lt[r] = s * T_SCL + bv[tg];
}

// ---------------- vocab: fp8 m16n8k32 mma + streaming exp-sum ----------------
// grid 128 = 32 mblk x 4 groups; 256 threads (8 warps, warp tile 32m x 64n).
// SMEM (bytes): A [128][528] fp8 | B 2x[128][80] fp8 | red [128][2] f32
#define V8_A_STRIDE 528
#define V8_B_OFF    67584
#define V8_B_SZ     10240
#define V8_B_STRIDE 80
#define V8_RED_OFF  88064
#define V8_SMEM     90112
extern __shared__ __align__(16) char dsm_v[];
__global__ void __launch_bounds__(256, 1) vocab_kernel() {
    const int tid = threadIdx.x, lane = tid & 31, wid = tid >> 5;
    const int wm = wid >> 1, wn = wid & 1;
    const int mblk = blockIdx.x >> 2, g = blockIdx.x & 3;
    const int gbase = g * GCOLS;

    // load A tile (128 rows x 512 fp8) into padded smem
    {
        const uint4* src = (const uint4*)(g_hq + (size_t)(mblk * 128) * HIDDEN);
        #pragma unroll
        for (int q = 0; q < 16; ++q) {
            int i = q * 256 + tid;                 // 4096 uint4
            int r = i >> 5, u = i & 31;
            *(uint4*)(dsm_v + r * V8_A_STRIDE + u * 16) = src[i];
        }
    }
    __syncthreads();

    const uint32_t a_base = smem_to_u32(dsm_v);
    const uint32_t a_lane = (uint32_t)((lane & 15) * V8_A_STRIDE + (lane >> 4) * 16);
    const uint32_t b_lane = (uint32_t)((((lane >> 3) & 1) * 8 + (lane & 7)) * V8_B_STRIDE + (lane >> 4) * 16);

    float rs[2][2] = {{0.f, 0.f}, {0.f, 0.f}};

    for (int tt = 0; tt < VTILES; ++tt) {
        const int nbase = gbase + tt * 128;
        float bb[16];
        {
            int cb = nbase + wn * 64 + (lane & 3) * 2;
            #pragma unroll
            for (int nt = 0; nt < 8; ++nt) {
                bb[nt * 2 + 0] = g_bv2[cb + nt * 8 + 0];
                bb[nt * 2 + 1] = g_bv2[cb + nt * 8 + 1];
            }
        }
        float d[2][8][4];
        #pragma unroll
        for (int mt = 0; mt < 2; ++mt)
            #pragma unroll
            for (int nt = 0; nt < 8; ++nt)
                #pragma unroll
                for (int e = 0; e < 4; ++e) d[mt][nt][e] = 0.f;

        // stage chunk 0 (8 KB)
        uint4 ld[2];
        #pragma unroll
        for (int q = 0; q < 2; ++q) {
            int i = q * 256 + tid;                // 512 uint4
            int n = i >> 2, u = i & 3;
            ld[q] = *(const uint4*)(g_wv8 + (size_t)(nbase + n) * HIDDEN + u * 16);
        }
        #pragma unroll
        for (int q = 0; q < 2; ++q) {
            int i = q * 256 + tid;
            int n = i >> 2, u = i & 3;
            *(uint4*)(dsm_v + V8_B_OFF + n * V8_B_STRIDE + u * 16) = ld[q];
        }
        __syncthreads();

        for (int kc = 0; kc < 8; ++kc) {
            if (kc < 7) {
                #pragma unroll
                for (int q = 0; q < 2; ++q) {
                    int i = q * 256 + tid;
                    int n = i >> 2, u = i & 3;
                    ld[q] = *(const uint4*)(g_wv8 + (size_t)(nbase + n) * HIDDEN + (kc + 1) * 64 + u * 16);
                }
            }
            const uint32_t b_base = smem_to_u32(dsm_v + V8_B_OFF + (kc & 1) * V8_B_SZ) +
                                    (uint32_t)(wn * 64 * V8_B_STRIDE);
            #pragma unroll
            for (int k32 = 0; k32 < 2; ++k32) {
                uint32_t a[2][4];
                #pragma unroll
                for (int mt = 0; mt < 2; ++mt) {
                    LDSM_X4(a[mt], a_base + a_lane +
                        (uint32_t)((wm * 32 + mt * 16) * V8_A_STRIDE + kc * 64 + k32 * 32));
                }
                #pragma unroll
                for (int np = 0; np < 4; ++np) {
                    uint32_t b[4];
                    LDSM_X4(b, b_base + b_lane + (uint32_t)(np * 16 * V8_B_STRIDE + k32 * 32));
                    // rows np*16+0..7 -> {b0,b2}; rows +8..15 -> {b1,b3}
                    MMA16832(d[0][np * 2 + 0], a[0], b[0], b[2]);
                    MMA16832(d[0][np * 2 + 1], a[0], b[1], b[3]);
                    MMA16832(d[1][np * 2 + 0], a[1], b[0], b[2]);
                    MMA16832(d[1][np * 2 + 1], a[1], b[1], b[3]);
                }
            }
            if (kc < 7) {
                char* dst = dsm_v + V8_B_OFF + ((kc + 1) & 1) * V8_B_SZ;
                #pragma unroll
                for (int q = 0; q < 2; ++q) {
                    int i = q * 256 + tid;
                    int n = i >> 2, u = i & 3;
                    *(uint4*)(dst + n * V8_B_STRIDE + u * 16) = ld[q];
                }
            }
            __syncthreads();
        }

        if (!(tt == VTILES - 1 && wn == 1)) {
            #pragma unroll
            for (int mt = 0; mt < 2; ++mt)
                #pragma unroll
                for (int rh = 0; rh < 2; ++rh) {
                    float s = 0.f;
                    #pragma unroll
                    for (int nt = 0; nt < 8; ++nt) {
                        s += exp2_fast(fmaf(d[mt][nt][rh * 2 + 0], V_SCL, bb[nt * 2 + 0]));
                        s += exp2_fast(fmaf(d[mt][nt][rh * 2 + 1], V_SCL, bb[nt * 2 + 1]));
                    }
                    rs[mt][rh] += s;
                }
        }
    }

    float* red = (float*)(dsm_v + V8_RED_OFF);
    #pragma unroll
    for (int mt = 0; mt < 2; ++mt)
        #pragma unroll
        for (int rh = 0; rh < 2; ++rh) {
            float v = rs[mt][rh];
            v += __shfl_xor_sync(0xffffffffu, v, 1);
            v += __shfl_xor_sync(0xffffffffu, v, 2);
            if ((lane & 3) == 0) {
                int row = wm * 32 + mt * 16 + rh * 8 + (lane >> 2);
                red[row * 2 + wn] = v;
            }
        }
    __syncthreads();
    if (tid < 128) {
        g_ps[g * MROWS + mblk * 128 + tid] = red[tid * 2 + 0] + red[tid * 2 + 1];
    }
}

// ---------------- combine ----------------
__global__ void __launch_bounds__(1024) combine_kernel(
    const int* __restrict__ captions, float* __restrict__ out)
{
    __shared__ float sh[1024];
    int tid = threadIdx.x;
    float local = 0.f;
    for (int r = tid; r < MROWS; r += 1024) {
        float S = g_ps[r] + g_ps[MROWS + r] + g_ps[2 * MROWS + r] + g_ps[3 * MROWS + r];
        int tg = captions[(r & 15) * 257 + (r >> 4) + 1];
        if (tg != 0) local += logf(S) - g_lt[r];
    }
    sh[tid] = local;
    __syncthreads();
    for (int o = 512; o > 0; o >>= 1) {
        if (tid < o) sh[tid] += sh[tid + o];
        __syncthreads();
    }
    if (tid == 0) out[0] = sh[0] * (1.f / NBATCH);
}

// ---------------- launch ----------------
extern "C" void kernel_launch(void* const* d_in, const int* in_sizes, int n_in,
                              void* d_out, int out_size) {
    const int*   captions = (const int*)d_in[0];
    const float* W_embed  = (const float*)d_in[1];
    const float* Wx       = (const float*)d_in[2];
    const float* Wh       = (const float*)d_in[3];
    const float* b        = (const float*)d_in[4];
    const float* W_vocab  = (const float*)d_in[5];
    const float* b_vocab  = (const float*)d_in[6];
    const float* h_init   = (const float*)d_in[7];

    cudaFuncSetAttribute(lstm_kernel,      cudaFuncAttributeMaxDynamicSharedMemorySize, 83200);
    cudaFuncSetAttribute(vocab_kernel,     cudaFuncAttributeMaxDynamicSharedMemorySize, V8_SMEM);
    cudaFuncSetAttribute(embed_mma_kernel, cudaFuncAttributeMaxDynamicSharedMemorySize, E_SMEM);

    init_kernel<<<32, 256>>>(h_init, b_vocab);
    gather_x_kernel<<<256, 256>>>(captions, W_embed);
    conv_wx_kernel<<<dim3(G4 / 32, WORDVEC / 32), 256>>>(Wx);
    conv_wv_kernel<<<dim3(VOCABSZ / 32, HIDDEN / 32), 256>>>(W_vocab);
    embed_mma_kernel<<<512, 256, E_SMEM>>>(b);
    lstm_kernel<<<128, 256, 83200>>>(Wh);
    tgt_kernel<<<512, 256>>>(captions, b_vocab);
    vocab_kernel<<<128, 256, V8_SMEM>>>();
    combine_kernel<<<1, 1024>>>(captions, (float*)d_out);
}